// round 1
// baseline (speedup 1.0000x reference)
#include <cuda_runtime.h>

#define IMG_H 512
#define IMG_W 512
#define TW 128                    // output tile width
#define TH 32                     // output tile height
#define HALO 5
#define RAW_W 144                 // TW + 2*HALO = 138, padded to 144 for alignment
#define RAW_H (TH + 2*HALO)       // 42
#define NF 5                      // i1, i2, i1*i1, i2*i2, i1*i2
#define NTHREADS 256

// reflect (mirror, no edge repeat) -- matches jnp.pad(mode='reflect')
__device__ __forceinline__ int reflect_idx(int i, int n) {
    i = (i < 0) ? -i : i;
    i = (i >= n) ? (2 * n - 2 - i) : i;
    return i;
}

__global__ void __launch_bounds__(NTHREADS, 1)
ssim_kernel(const float* __restrict__ img1, const float* __restrict__ img2,
            float* __restrict__ out)
{
    // Normalized 1D Gaussian, ws=11, sigma=1.5 (compile-time immediates -> FFMA-imm)
    constexpr float G[11] = {
        0.00102838f, 0.00759876f, 0.03600077f, 0.10936071f, 0.21300554f,
        0.26601172f,
        0.21300554f, 0.10936071f, 0.03600077f, 0.00759876f, 0.00102838f
    };

    extern __shared__ float sm[];
    float* raw1 = sm;                           // [RAW_H][RAW_W]
    float* raw2 = sm + RAW_H * RAW_W;           // [RAW_H][RAW_W]
    float* hb   = sm + 2 * RAW_H * RAW_W;       // [NF][RAW_H][TW]

    const int tx0 = blockIdx.x * TW;
    const int ty0 = blockIdx.y * TH;
    const long long planeOff = (long long)blockIdx.z * (IMG_H * IMG_W);
    const float* p1 = img1 + planeOff;
    const float* p2 = img2 + planeOff;
    const int t = threadIdx.x;

    // ---------------- Phase 0: stage raw tiles (with reflect halo) ----------------
    for (int idx = t; idx < RAW_H * RAW_W; idx += NTHREADS) {
        int r = idx / RAW_W;
        int c = idx - r * RAW_W;
        int gy = reflect_idx(ty0 + r - HALO, IMG_H);
        int gx = reflect_idx(tx0 + c - HALO, IMG_W);
        long long g = (long long)gy * IMG_W + gx;
        raw1[idx] = p1[g];
        raw2[idx] = p2[g];
    }
    __syncthreads();

    // ---------------- Phase 1: horizontal 11-tap conv of the 5 fields -------------
    // Each task = 4 consecutive output columns of one raw row. Vec4 LDS, products
    // computed once per element, taps as immediates.
    for (int idx = t; idx < RAW_H * (TW / 4); idx += NTHREADS) {
        int rr = idx >> 5;              // idx / 32  (TW/4 == 32)
        int c  = (idx & 31) << 2;
        const float4* r1 = (const float4*)(raw1 + rr * RAW_W + c);
        const float4* r2 = (const float4*)(raw2 + rr * RAW_W + c);
        float x1[16], x2[16];
        #pragma unroll
        for (int q = 0; q < 4; ++q) {
            float4 v1 = r1[q];
            float4 v2 = r2[q];
            x1[4*q+0] = v1.x; x1[4*q+1] = v1.y; x1[4*q+2] = v1.z; x1[4*q+3] = v1.w;
            x2[4*q+0] = v2.x; x2[4*q+1] = v2.y; x2[4*q+2] = v2.z; x2[4*q+3] = v2.w;
        }
        float p11[14], p22[14], p12[14];
        #pragma unroll
        for (int j = 0; j < 14; ++j) {
            p11[j] = x1[j] * x1[j];
            p22[j] = x2[j] * x2[j];
            p12[j] = x1[j] * x2[j];
        }
        float s1[4]  = {0.f,0.f,0.f,0.f}, s2[4]  = {0.f,0.f,0.f,0.f};
        float s11[4] = {0.f,0.f,0.f,0.f}, s22[4] = {0.f,0.f,0.f,0.f};
        float s12[4] = {0.f,0.f,0.f,0.f};
        #pragma unroll
        for (int k = 0; k < 11; ++k) {
            const float g = G[k];
            #pragma unroll
            for (int o = 0; o < 4; ++o) {
                s1[o]  += g * x1[o + k];
                s2[o]  += g * x2[o + k];
                s11[o] += g * p11[o + k];
                s22[o] += g * p22[o + k];
                s12[o] += g * p12[o + k];
            }
        }
        float* hp = hb + rr * TW + c;
        *(float4*)(hp + 0 * RAW_H * TW) = make_float4(s1[0],  s1[1],  s1[2],  s1[3]);
        *(float4*)(hp + 1 * RAW_H * TW) = make_float4(s2[0],  s2[1],  s2[2],  s2[3]);
        *(float4*)(hp + 2 * RAW_H * TW) = make_float4(s11[0], s11[1], s11[2], s11[3]);
        *(float4*)(hp + 3 * RAW_H * TW) = make_float4(s22[0], s22[1], s22[2], s22[3]);
        *(float4*)(hp + 4 * RAW_H * TW) = make_float4(s12[0], s12[1], s12[2], s12[3]);
    }
    __syncthreads();

    // ---------------- Phase 2: vertical 11-tap conv + SSIM epilogue ---------------
    // Thread owns one column, 16 output rows -> 80 independent reg accumulators.
    {
        const int c  = t & (TW - 1);
        const int r0 = (t >> 7) * (TH / 2);   // 0 or 16
        float acc[NF][TH / 2];
        #pragma unroll
        for (int f = 0; f < NF; ++f)
            #pragma unroll
            for (int i = 0; i < TH / 2; ++i) acc[f][i] = 0.f;

        #pragma unroll
        for (int rr = 0; rr < TH / 2 + 2 * HALO; ++rr) {   // 26 h-rows
            float v[NF];
            #pragma unroll
            for (int f = 0; f < NF; ++f)
                v[f] = hb[(f * RAW_H + r0 + rr) * TW + c];
            #pragma unroll
            for (int k = 0; k < 11; ++k) {
                const int r = rr - k;
                if (r >= 0 && r < TH / 2) {
                    #pragma unroll
                    for (int f = 0; f < NF; ++f)
                        acc[f][r] += G[k] * v[f];
                }
            }
        }

        const float C1 = 1.0e-4f;   // (0.01*1.0)^2
        const float C2 = 9.0e-4f;   // (0.03*1.0)^2
        float* op = out + planeOff + (long long)(ty0 + r0) * IMG_W + tx0 + c;
        #pragma unroll
        for (int i = 0; i < TH / 2; ++i) {
            float mu1 = acc[0][i], mu2 = acc[1][i];
            float m11 = mu1 * mu1, m22 = mu2 * mu2, m12 = mu1 * mu2;
            float sg1 = acc[2][i] - m11;
            float sg2 = acc[3][i] - m22;
            float sg12 = acc[4][i] - m12;
            float num = fmaf(2.f, m12, C1) * fmaf(2.f, sg12, C2);
            float den = (m11 + m22 + C1) * (sg1 + sg2 + C2);
            op[(long long)i * IMG_W] = __fdividef(num, den);
        }
    }
}

extern "C" void kernel_launch(void* const* d_in, const int* in_sizes, int n_in,
                              void* d_out, int out_size) {
    const float* img1 = (const float*)d_in[0];
    const float* img2 = (const float*)d_in[1];
    // d_in[2] is the 11x11 gaussian window; it is a fixed function of
    // WINDOW_SIZE=11, SIGMA=1.5 and is baked into the kernel as immediates.
    float* out = (float*)d_out;

    const int planes = out_size / (IMG_H * IMG_W);   // 16*3 = 48
    constexpr int SMEM = (2 * RAW_H * RAW_W + NF * RAW_H * TW) * (int)sizeof(float);
    cudaFuncSetAttribute(ssim_kernel,
                         cudaFuncAttributeMaxDynamicSharedMemorySize, SMEM);
    dim3 grid(IMG_W / TW, IMG_H / TH, planes);
    ssim_kernel<<<grid, NTHREADS, SMEM>>>(img1, img2, out);
}

// round 2
// speedup vs baseline: 1.5457x; 1.5457x over previous
#include <cuda_runtime.h>

#define IMG_H 512
#define IMG_W 512
#define TW 128                    // output tile width
#define TH 16                     // output tile height (shrunk: 2 CTAs/SM)
#define HALO 5
#define RAW_W 144                 // TW + 2*HALO = 138, padded to 144 for alignment
#define RAW_H (TH + 2*HALO)       // 26
#define NF 5                      // i1, i2, i1*i1, i2*i2, i1*i2
#define NTHREADS 512
#define ROWS_PT 4                 // output rows per thread in vertical pass (512 thr / 128 col)

// reflect (mirror, no edge repeat) -- matches jnp.pad(mode='reflect')
__device__ __forceinline__ int reflect_idx(int i, int n) {
    i = (i < 0) ? -i : i;
    i = (i >= n) ? (2 * n - 2 - i) : i;
    return i;
}

__global__ void __launch_bounds__(NTHREADS, 2)
ssim_kernel(const float* __restrict__ img1, const float* __restrict__ img2,
            float* __restrict__ out)
{
    // Normalized 1D Gaussian, ws=11, sigma=1.5 (compile-time immediates -> FFMA-imm)
    constexpr float G[11] = {
        0.00102838f, 0.00759876f, 0.03600077f, 0.10936071f, 0.21300554f,
        0.26601172f,
        0.21300554f, 0.10936071f, 0.03600077f, 0.00759876f, 0.00102838f
    };

    extern __shared__ float sm[];
    float* raw1 = sm;                           // [RAW_H][RAW_W]
    float* raw2 = sm + RAW_H * RAW_W;           // [RAW_H][RAW_W]
    float* hb   = sm + 2 * RAW_H * RAW_W;       // [NF][RAW_H][TW]

    const int tx0 = blockIdx.x * TW;
    const int ty0 = blockIdx.y * TH;
    const long long planeOff = (long long)blockIdx.z * (IMG_H * IMG_W);
    const float* p1 = img1 + planeOff;
    const float* p2 = img2 + planeOff;
    const int t = threadIdx.x;

    // ---------------- Phase 0: stage raw tiles (with reflect halo) ----------------
    #pragma unroll
    for (int idx = t; idx < RAW_H * RAW_W; idx += NTHREADS) {
        int r = idx / RAW_W;
        int c = idx - r * RAW_W;
        int gy = reflect_idx(ty0 + r - HALO, IMG_H);
        int gx = reflect_idx(tx0 + c - HALO, IMG_W);
        long long g = (long long)gy * IMG_W + gx;
        raw1[idx] = p1[g];
        raw2[idx] = p2[g];
    }
    __syncthreads();

    // ---------------- Phase 1: horizontal 11-tap conv of the 5 fields -------------
    // Each task = 4 consecutive output columns of one raw row. Vec4 LDS, products
    // computed once per element, taps as immediates.
    for (int idx = t; idx < RAW_H * (TW / 4); idx += NTHREADS) {
        int rr = idx >> 5;              // idx / 32  (TW/4 == 32)
        int c  = (idx & 31) << 2;
        const float4* r1 = (const float4*)(raw1 + rr * RAW_W + c);
        const float4* r2 = (const float4*)(raw2 + rr * RAW_W + c);
        float x1[16], x2[16];
        #pragma unroll
        for (int q = 0; q < 4; ++q) {
            float4 v1 = r1[q];
            float4 v2 = r2[q];
            x1[4*q+0] = v1.x; x1[4*q+1] = v1.y; x1[4*q+2] = v1.z; x1[4*q+3] = v1.w;
            x2[4*q+0] = v2.x; x2[4*q+1] = v2.y; x2[4*q+2] = v2.z; x2[4*q+3] = v2.w;
        }
        float p11[14], p22[14], p12[14];
        #pragma unroll
        for (int j = 0; j < 14; ++j) {
            p11[j] = x1[j] * x1[j];
            p22[j] = x2[j] * x2[j];
            p12[j] = x1[j] * x2[j];
        }
        float s1[4]  = {0.f,0.f,0.f,0.f}, s2[4]  = {0.f,0.f,0.f,0.f};
        float s11[4] = {0.f,0.f,0.f,0.f}, s22[4] = {0.f,0.f,0.f,0.f};
        float s12[4] = {0.f,0.f,0.f,0.f};
        #pragma unroll
        for (int k = 0; k < 11; ++k) {
            const float g = G[k];
            #pragma unroll
            for (int o = 0; o < 4; ++o) {
                s1[o]  += g * x1[o + k];
                s2[o]  += g * x2[o + k];
                s11[o] += g * p11[o + k];
                s22[o] += g * p22[o + k];
                s12[o] += g * p12[o + k];
            }
        }
        float* hp = hb + rr * TW + c;
        *(float4*)(hp + 0 * RAW_H * TW) = make_float4(s1[0],  s1[1],  s1[2],  s1[3]);
        *(float4*)(hp + 1 * RAW_H * TW) = make_float4(s2[0],  s2[1],  s2[2],  s2[3]);
        *(float4*)(hp + 2 * RAW_H * TW) = make_float4(s11[0], s11[1], s11[2], s11[3]);
        *(float4*)(hp + 3 * RAW_H * TW) = make_float4(s22[0], s22[1], s22[2], s22[3]);
        *(float4*)(hp + 4 * RAW_H * TW) = make_float4(s12[0], s12[1], s12[2], s12[3]);
    }
    __syncthreads();

    // ---------------- Phase 2: vertical 11-tap conv + SSIM epilogue ---------------
    // Thread owns one column x ROWS_PT output rows -> 20 independent reg accumulators.
    {
        const int c  = t & (TW - 1);
        const int r0 = (t >> 7) * ROWS_PT;   // 0,4,8,12
        float acc[NF][ROWS_PT];
        #pragma unroll
        for (int f = 0; f < NF; ++f)
            #pragma unroll
            for (int i = 0; i < ROWS_PT; ++i) acc[f][i] = 0.f;

        #pragma unroll
        for (int rr = 0; rr < ROWS_PT + 2 * HALO; ++rr) {   // 14 h-rows
            float v[NF];
            #pragma unroll
            for (int f = 0; f < NF; ++f)
                v[f] = hb[(f * RAW_H + r0 + rr) * TW + c];
            #pragma unroll
            for (int k = 0; k < 11; ++k) {
                const int r = rr - k;
                if (r >= 0 && r < ROWS_PT) {
                    #pragma unroll
                    for (int f = 0; f < NF; ++f)
                        acc[f][r] += G[k] * v[f];
                }
            }
        }

        const float C1 = 1.0e-4f;   // (0.01*1.0)^2
        const float C2 = 9.0e-4f;   // (0.03*1.0)^2
        float* op = out + planeOff + (long long)(ty0 + r0) * IMG_W + tx0 + c;
        #pragma unroll
        for (int i = 0; i < ROWS_PT; ++i) {
            float mu1 = acc[0][i], mu2 = acc[1][i];
            float m11 = mu1 * mu1, m22 = mu2 * mu2, m12 = mu1 * mu2;
            float sg1 = acc[2][i] - m11;
            float sg2 = acc[3][i] - m22;
            float sg12 = acc[4][i] - m12;
            float num = fmaf(2.f, m12, C1) * fmaf(2.f, sg12, C2);
            float den = (m11 + m22 + C1) * (sg1 + sg2 + C2);
            op[(long long)i * IMG_W] = __fdividef(num, den);
        }
    }
}

extern "C" void kernel_launch(void* const* d_in, const int* in_sizes, int n_in,
                              void* d_out, int out_size) {
    const float* img1 = (const float*)d_in[0];
    const float* img2 = (const float*)d_in[1];
    // d_in[2] is the 11x11 gaussian window; it is a fixed function of
    // WINDOW_SIZE=11, SIGMA=1.5 and is baked into the kernel as immediates.
    float* out = (float*)d_out;

    const int planes = out_size / (IMG_H * IMG_W);   // 16*3 = 48
    constexpr int SMEM = (2 * RAW_H * RAW_W + NF * RAW_H * TW) * (int)sizeof(float);
    cudaFuncSetAttribute(ssim_kernel,
                         cudaFuncAttributeMaxDynamicSharedMemorySize, SMEM);
    dim3 grid(IMG_W / TW, IMG_H / TH, planes);
    ssim_kernel<<<grid, NTHREADS, SMEM>>>(img1, img2, out);
}

// round 3
// speedup vs baseline: 1.5486x; 1.0019x over previous
#include <cuda_runtime.h>

#define IMG_H 512
#define IMG_W 512
#define TW 128                    // output tile width
#define TH 16                     // output tile height (shrunk: 2 CTAs/SM)
#define HALO 5
#define RAW_W 144                 // TW + 2*HALO = 138, padded to 144 for alignment
#define RAW_H (TH + 2*HALO)       // 26
#define NF 5                      // i1, i2, i1*i1, i2*i2, i1*i2
#define NTHREADS 512
#define ROWS_PT 4                 // output rows per thread in vertical pass (512 thr / 128 col)

// reflect (mirror, no edge repeat) -- matches jnp.pad(mode='reflect')
__device__ __forceinline__ int reflect_idx(int i, int n) {
    i = (i < 0) ? -i : i;
    i = (i >= n) ? (2 * n - 2 - i) : i;
    return i;
}

__global__ void __launch_bounds__(NTHREADS, 2)
ssim_kernel(const float* __restrict__ img1, const float* __restrict__ img2,
            float* __restrict__ out)
{
    // Normalized 1D Gaussian, ws=11, sigma=1.5 (compile-time immediates -> FFMA-imm)
    constexpr float G[11] = {
        0.00102838f, 0.00759876f, 0.03600077f, 0.10936071f, 0.21300554f,
        0.26601172f,
        0.21300554f, 0.10936071f, 0.03600077f, 0.00759876f, 0.00102838f
    };

    extern __shared__ float sm[];
    float* raw1 = sm;                           // [RAW_H][RAW_W]
    float* raw2 = sm + RAW_H * RAW_W;           // [RAW_H][RAW_W]
    float* hb   = sm + 2 * RAW_H * RAW_W;       // [NF][RAW_H][TW]

    const int tx0 = blockIdx.x * TW;
    const int ty0 = blockIdx.y * TH;
    const long long planeOff = (long long)blockIdx.z * (IMG_H * IMG_W);
    const float* p1 = img1 + planeOff;
    const float* p2 = img2 + planeOff;
    const int t = threadIdx.x;

    // ---------------- Phase 0: stage raw tiles (with reflect halo) ----------------
    #pragma unroll
    for (int idx = t; idx < RAW_H * RAW_W; idx += NTHREADS) {
        int r = idx / RAW_W;
        int c = idx - r * RAW_W;
        int gy = reflect_idx(ty0 + r - HALO, IMG_H);
        int gx = reflect_idx(tx0 + c - HALO, IMG_W);
        long long g = (long long)gy * IMG_W + gx;
        raw1[idx] = p1[g];
        raw2[idx] = p2[g];
    }
    __syncthreads();

    // ---------------- Phase 1: horizontal 11-tap conv of the 5 fields -------------
    // Each task = 4 consecutive output columns of one raw row. Vec4 LDS, products
    // computed once per element, taps as immediates.
    for (int idx = t; idx < RAW_H * (TW / 4); idx += NTHREADS) {
        int rr = idx >> 5;              // idx / 32  (TW/4 == 32)
        int c  = (idx & 31) << 2;
        const float4* r1 = (const float4*)(raw1 + rr * RAW_W + c);
        const float4* r2 = (const float4*)(raw2 + rr * RAW_W + c);
        float x1[16], x2[16];
        #pragma unroll
        for (int q = 0; q < 4; ++q) {
            float4 v1 = r1[q];
            float4 v2 = r2[q];
            x1[4*q+0] = v1.x; x1[4*q+1] = v1.y; x1[4*q+2] = v1.z; x1[4*q+3] = v1.w;
            x2[4*q+0] = v2.x; x2[4*q+1] = v2.y; x2[4*q+2] = v2.z; x2[4*q+3] = v2.w;
        }
        float p11[14], p22[14], p12[14];
        #pragma unroll
        for (int j = 0; j < 14; ++j) {
            p11[j] = x1[j] * x1[j];
            p22[j] = x2[j] * x2[j];
            p12[j] = x1[j] * x2[j];
        }
        float s1[4]  = {0.f,0.f,0.f,0.f}, s2[4]  = {0.f,0.f,0.f,0.f};
        float s11[4] = {0.f,0.f,0.f,0.f}, s22[4] = {0.f,0.f,0.f,0.f};
        float s12[4] = {0.f,0.f,0.f,0.f};
        #pragma unroll
        for (int k = 0; k < 11; ++k) {
            const float g = G[k];
            #pragma unroll
            for (int o = 0; o < 4; ++o) {
                s1[o]  += g * x1[o + k];
                s2[o]  += g * x2[o + k];
                s11[o] += g * p11[o + k];
                s22[o] += g * p22[o + k];
                s12[o] += g * p12[o + k];
            }
        }
        float* hp = hb + rr * TW + c;
        *(float4*)(hp + 0 * RAW_H * TW) = make_float4(s1[0],  s1[1],  s1[2],  s1[3]);
        *(float4*)(hp + 1 * RAW_H * TW) = make_float4(s2[0],  s2[1],  s2[2],  s2[3]);
        *(float4*)(hp + 2 * RAW_H * TW) = make_float4(s11[0], s11[1], s11[2], s11[3]);
        *(float4*)(hp + 3 * RAW_H * TW) = make_float4(s22[0], s22[1], s22[2], s22[3]);
        *(float4*)(hp + 4 * RAW_H * TW) = make_float4(s12[0], s12[1], s12[2], s12[3]);
    }
    __syncthreads();

    // ---------------- Phase 2: vertical 11-tap conv + SSIM epilogue ---------------
    // Thread owns one column x ROWS_PT output rows -> 20 independent reg accumulators.
    {
        const int c  = t & (TW - 1);
        const int r0 = (t >> 7) * ROWS_PT;   // 0,4,8,12
        float acc[NF][ROWS_PT];
        #pragma unroll
        for (int f = 0; f < NF; ++f)
            #pragma unroll
            for (int i = 0; i < ROWS_PT; ++i) acc[f][i] = 0.f;

        #pragma unroll
        for (int rr = 0; rr < ROWS_PT + 2 * HALO; ++rr) {   // 14 h-rows
            float v[NF];
            #pragma unroll
            for (int f = 0; f < NF; ++f)
                v[f] = hb[(f * RAW_H + r0 + rr) * TW + c];
            #pragma unroll
            for (int k = 0; k < 11; ++k) {
                const int r = rr - k;
                if (r >= 0 && r < ROWS_PT) {
                    #pragma unroll
                    for (int f = 0; f < NF; ++f)
                        acc[f][r] += G[k] * v[f];
                }
            }
        }

        const float C1 = 1.0e-4f;   // (0.01*1.0)^2
        const float C2 = 9.0e-4f;   // (0.03*1.0)^2
        float* op = out + planeOff + (long long)(ty0 + r0) * IMG_W + tx0 + c;
        #pragma unroll
        for (int i = 0; i < ROWS_PT; ++i) {
            float mu1 = acc[0][i], mu2 = acc[1][i];
            float m11 = mu1 * mu1, m22 = mu2 * mu2, m12 = mu1 * mu2;
            float sg1 = acc[2][i] - m11;
            float sg2 = acc[3][i] - m22;
            float sg12 = acc[4][i] - m12;
            float num = fmaf(2.f, m12, C1) * fmaf(2.f, sg12, C2);
            float den = (m11 + m22 + C1) * (sg1 + sg2 + C2);
            op[(long long)i * IMG_W] = __fdividef(num, den);
        }
    }
}

extern "C" void kernel_launch(void* const* d_in, const int* in_sizes, int n_in,
                              void* d_out, int out_size) {
    const float* img1 = (const float*)d_in[0];
    const float* img2 = (const float*)d_in[1];
    // d_in[2] is the 11x11 gaussian window; it is a fixed function of
    // WINDOW_SIZE=11, SIGMA=1.5 and is baked into the kernel as immediates.
    float* out = (float*)d_out;

    const int planes = out_size / (IMG_H * IMG_W);   // 16*3 = 48
    constexpr int SMEM = (2 * RAW_H * RAW_W + NF * RAW_H * TW) * (int)sizeof(float);
    cudaFuncSetAttribute(ssim_kernel,
                         cudaFuncAttributeMaxDynamicSharedMemorySize, SMEM);
    dim3 grid(IMG_W / TW, IMG_H / TH, planes);
    ssim_kernel<<<grid, NTHREADS, SMEM>>>(img1, img2, out);
}